// round 1
// baseline (speedup 1.0000x reference)
#include <cuda_runtime.h>
#include <cuda_bf16.h>
#include <stdint.h>

// Problem constants
#define NTOK   (32 * 8192)          // 262144 tokens
#define TILE_T 128                  // tokens per CTA tile (4 warps x 32)
#define NTILES (NTOK / TILE_T)      // 2048
#define KPAD   36                   // words per smem W row (72 bf16, conflict-free)

// Split one float pair into bf16-hi and bf16-lo packed words (lo = residual).
__device__ __forceinline__ void split2(float x0, float x1, uint32_t& hi, uint32_t& lo) {
    __nv_bfloat16 h0 = __float2bfloat16(x0);
    __nv_bfloat16 h1 = __float2bfloat16(x1);
    __nv_bfloat16 l0 = __float2bfloat16(x0 - __bfloat162float(h0));
    __nv_bfloat16 l1 = __float2bfloat16(x1 - __bfloat162float(h1));
    hi = (uint32_t)__bfloat16_as_ushort(h0) | ((uint32_t)__bfloat16_as_ushort(h1) << 16);
    lo = (uint32_t)__bfloat16_as_ushort(l0) | ((uint32_t)__bfloat16_as_ushort(l1) << 16);
}

__device__ __forceinline__ void mma16816(float* c, const uint32_t* a, uint32_t b0, uint32_t b1) {
    asm volatile(
        "mma.sync.aligned.m16n8k16.row.col.f32.bf16.bf16.f32 "
        "{%0,%1,%2,%3}, {%4,%5,%6,%7}, {%8,%9}, {%0,%1,%2,%3};\n"
        : "+f"(c[0]), "+f"(c[1]), "+f"(c[2]), "+f"(c[3])
        : "r"(a[0]), "r"(a[1]), "r"(a[2]), "r"(a[3]), "r"(b0), "r"(b1));
}

__global__ void __launch_bounds__(128)
quantum_fused_kernel(const float* __restrict__ x,
                     const float* __restrict__ Win,    // [64 wires][64 embed]
                     const float* __restrict__ theta,  // [64]
                     const float* __restrict__ Wout,   // [64 out][64 wires]
                     float* __restrict__ out)
{
    // Weight splits in smem, row-major [n][k] (exactly the gmem layout since
    // B-operand for "X @ W^T" col-major frag == W row-major), padded to 36 words.
    __shared__ uint32_t sWinHi[64 * KPAD];
    __shared__ uint32_t sWinLo[64 * KPAD];
    __shared__ uint32_t sWoutHi[64 * KPAD];
    __shared__ uint32_t sWoutLo[64 * KPAD];
    __shared__ float    sTheta[64];

    const int tid = threadIdx.x;

    // One-time W split: 64 rows x 32 words, 128 threads.
    for (int idx = tid; idx < 64 * 32; idx += 128) {
        int row = idx >> 5, w = idx & 31;
        float2 v = ((const float2*)Win)[row * 32 + w];
        uint32_t h, l;
        split2(v.x, v.y, h, l);
        sWinHi[row * KPAD + w] = h;
        sWinLo[row * KPAD + w] = l;
        v = ((const float2*)Wout)[row * 32 + w];
        split2(v.x, v.y, h, l);
        sWoutHi[row * KPAD + w] = h;
        sWoutLo[row * KPAD + w] = l;
    }
    if (tid < 64) sTheta[tid] = theta[tid];
    __syncthreads();

    const int lane = tid & 31;
    const int warp = tid >> 5;
    const int gr   = lane >> 2;   // group-of-4 id (row within 8)
    const int tc   = lane & 3;    // thread-in-group (col pair selector)

    // Hoist theta into registers: col = nt*8 + tc*2 (+1)
    float th0[8], th1[8];
#pragma unroll
    for (int nt = 0; nt < 8; nt++) {
        th0[nt] = sTheta[nt * 8 + tc * 2];
        th1[nt] = sTheta[nt * 8 + tc * 2 + 1];
    }

    for (int tile = blockIdx.x; tile < NTILES; tile += gridDim.x) {
        const int tok0 = tile * TILE_T + warp * 32;   // 32 tokens (2 m-tiles) per warp

        // ---------------- GEMM1: T = X @ Win^T (bf16x3, fp32 acc) ----------------
        float acc[2][8][4];
#pragma unroll
        for (int mt = 0; mt < 2; mt++)
#pragma unroll
            for (int nt = 0; nt < 8; nt++)
#pragma unroll
                for (int i = 0; i < 4; i++) acc[mt][nt][i] = 0.f;

#pragma unroll
        for (int kt = 0; kt < 4; kt++) {
            uint32_t ah[2][4], al[2][4];
#pragma unroll
            for (int mt = 0; mt < 2; mt++) {
                const size_t r0 = (size_t)(tok0 + mt * 16 + gr);
                const float* p  = x + r0 * 64 + kt * 16 + tc * 2;
                float2 v00 = *(const float2*)(p);             // (gr,   tc*2)
                float2 v10 = *(const float2*)(p + 8 * 64);    // (gr+8, tc*2)
                float2 v01 = *(const float2*)(p + 8);         // (gr,   tc*2+8)
                float2 v11 = *(const float2*)(p + 8 * 64 + 8);// (gr+8, tc*2+8)
                split2(v00.x, v00.y, ah[mt][0], al[mt][0]);
                split2(v10.x, v10.y, ah[mt][1], al[mt][1]);
                split2(v01.x, v01.y, ah[mt][2], al[mt][2]);
                split2(v11.x, v11.y, ah[mt][3], al[mt][3]);
            }
#pragma unroll
            for (int nt = 0; nt < 8; nt++) {
                const int bidx = (nt * 8 + gr) * KPAD + kt * 8 + tc;
                const uint32_t bh0 = sWinHi[bidx], bh1 = sWinHi[bidx + 4];
                const uint32_t bl0 = sWinLo[bidx], bl1 = sWinLo[bidx + 4];
#pragma unroll
                for (int mt = 0; mt < 2; mt++) {
                    mma16816(acc[mt][nt], ah[mt], bh0, bh1);  // hi*hi
                    mma16816(acc[mt][nt], al[mt], bh0, bh1);  // lo*hi
                    mma16816(acc[mt][nt], ah[mt], bl0, bl1);  // hi*lo
                }
            }
        }

        // -------- q = cos(T + theta); repack C-frags directly into A-frags --------
        uint32_t a2h[2][4][4], a2l[2][4][4];
#pragma unroll
        for (int mt = 0; mt < 2; mt++) {
#pragma unroll
            for (int kt2 = 0; kt2 < 4; kt2++) {
                const int ntA = 2 * kt2, ntB = 2 * kt2 + 1;
                float qa0 = cosf(acc[mt][ntA][0] + th0[ntA]);
                float qa1 = cosf(acc[mt][ntA][1] + th1[ntA]);
                float qa2 = cosf(acc[mt][ntA][2] + th0[ntA]);
                float qa3 = cosf(acc[mt][ntA][3] + th1[ntA]);
                float qb0 = cosf(acc[mt][ntB][0] + th0[ntB]);
                float qb1 = cosf(acc[mt][ntB][1] + th1[ntB]);
                float qb2 = cosf(acc[mt][ntB][2] + th0[ntB]);
                float qb3 = cosf(acc[mt][ntB][3] + th1[ntB]);
                split2(qa0, qa1, a2h[mt][kt2][0], a2l[mt][kt2][0]); // row gr,   k lo-half
                split2(qa2, qa3, a2h[mt][kt2][1], a2l[mt][kt2][1]); // row gr+8, k lo-half
                split2(qb0, qb1, a2h[mt][kt2][2], a2l[mt][kt2][2]); // row gr,   k hi-half
                split2(qb2, qb3, a2h[mt][kt2][3], a2l[mt][kt2][3]); // row gr+8, k hi-half
            }
        }

        // ---------------- GEMM2: Y = q @ Wout^T (bf16x3, fp32 acc) ----------------
        float acc2[2][8][4];
#pragma unroll
        for (int mt = 0; mt < 2; mt++)
#pragma unroll
            for (int nt = 0; nt < 8; nt++)
#pragma unroll
                for (int i = 0; i < 4; i++) acc2[mt][nt][i] = 0.f;

#pragma unroll
        for (int kt2 = 0; kt2 < 4; kt2++) {
#pragma unroll
            for (int nt2 = 0; nt2 < 8; nt2++) {
                const int bidx = (nt2 * 8 + gr) * KPAD + kt2 * 8 + tc;
                const uint32_t bh0 = sWoutHi[bidx], bh1 = sWoutHi[bidx + 4];
                const uint32_t bl0 = sWoutLo[bidx], bl1 = sWoutLo[bidx + 4];
#pragma unroll
                for (int mt = 0; mt < 2; mt++) {
                    mma16816(acc2[mt][nt2], a2h[mt][kt2], bh0, bh1);
                    mma16816(acc2[mt][nt2], a2l[mt][kt2], bh0, bh1);
                    mma16816(acc2[mt][nt2], a2h[mt][kt2], bl0, bl1);
                }
            }
        }

        // ---------------- Store: each 4-lane group writes contiguous 32B ----------------
#pragma unroll
        for (int mt = 0; mt < 2; mt++) {
            const size_t r0 = (size_t)(tok0 + mt * 16 + gr);
#pragma unroll
            for (int nt2 = 0; nt2 < 8; nt2++) {
                float* po = out + r0 * 64 + nt2 * 8 + tc * 2;
                *(float2*)po            = make_float2(acc2[mt][nt2][0], acc2[mt][nt2][1]);
                *(float2*)(po + 8 * 64) = make_float2(acc2[mt][nt2][2], acc2[mt][nt2][3]);
            }
        }
    }
}

extern "C" void kernel_launch(void* const* d_in, const int* in_sizes, int n_in,
                              void* d_out, int out_size) {
    const float* x     = (const float*)d_in[0];
    const float* W_in  = (const float*)d_in[1];
    const float* theta = (const float*)d_in[2];
    const float* W_out = (const float*)d_in[3];
    float* out = (float*)d_out;

    // Grid-strided over 2048 tiles; 444 CTAs (3/SM target) keeps the per-CTA
    // weight-split amortized and wave-balanced.
    quantum_fused_kernel<<<444, 128>>>(x, W_in, theta, W_out, out);
}

// round 2
// speedup vs baseline: 2.1245x; 2.1245x over previous
#include <cuda_runtime.h>
#include <cuda_bf16.h>
#include <stdint.h>

// Problem constants
#define NTOK   (32 * 8192)          // 262144 tokens
#define TILE_T 128                  // tokens per CTA (8 warps x 16)
#define NCTAS  (NTOK / TILE_T)      // 2048
#define KPAD   36                   // words per smem W row (72 bf16, conflict-free)

// Split one float pair into bf16-hi and bf16-lo packed words (lo = residual).
__device__ __forceinline__ void split2(float x0, float x1, uint32_t& hi, uint32_t& lo) {
    __nv_bfloat16 h0 = __float2bfloat16(x0);
    __nv_bfloat16 h1 = __float2bfloat16(x1);
    __nv_bfloat16 l0 = __float2bfloat16(x0 - __bfloat162float(h0));
    __nv_bfloat16 l1 = __float2bfloat16(x1 - __bfloat162float(h1));
    hi = (uint32_t)__bfloat16_as_ushort(h0) | ((uint32_t)__bfloat16_as_ushort(h1) << 16);
    lo = (uint32_t)__bfloat16_as_ushort(l0) | ((uint32_t)__bfloat16_as_ushort(l1) << 16);
}

__device__ __forceinline__ void mma16816(float* c, const uint32_t* a, uint32_t b0, uint32_t b1) {
    asm volatile(
        "mma.sync.aligned.m16n8k16.row.col.f32.bf16.bf16.f32 "
        "{%0,%1,%2,%3}, {%4,%5,%6,%7}, {%8,%9}, {%0,%1,%2,%3};\n"
        : "+f"(c[0]), "+f"(c[1]), "+f"(c[2]), "+f"(c[3])
        : "r"(a[0]), "r"(a[1]), "r"(a[2]), "r"(a[3]), "r"(b0), "r"(b1));
}

__device__ __forceinline__ float2 ldcs2(const float* p) {
    float2 v;
    asm volatile("ld.global.cs.v2.f32 {%0,%1}, [%2];" : "=f"(v.x), "=f"(v.y) : "l"(p));
    return v;
}
__device__ __forceinline__ void stcs2(float* p, float a, float b) {
    asm volatile("st.global.cs.v2.f32 [%0], {%1,%2};" :: "l"(p), "f"(a), "f"(b));
}

__global__ void __launch_bounds__(256, 2)
quantum_fused_kernel(const float* __restrict__ x,
                     const float* __restrict__ Win,    // [64 wires][64 embed]
                     const float* __restrict__ theta,  // [64]
                     const float* __restrict__ Wout,   // [64 out][64 wires]
                     float* __restrict__ out)
{
    // Weight splits in smem, row-major [n][k], padded rows (conflict-free frag reads).
    __shared__ uint32_t sWinHi[64 * KPAD];
    __shared__ uint32_t sWinLo[64 * KPAD];
    __shared__ uint32_t sWoutHi[64 * KPAD];
    __shared__ uint32_t sWoutLo[64 * KPAD];
    __shared__ float    sTheta[64];

    const int tid = threadIdx.x;

    // One-time W split: 64 rows x 32 words, 256 threads -> 8 iters each.
    for (int idx = tid; idx < 64 * 32; idx += 256) {
        int row = idx >> 5, w = idx & 31;
        float2 v = ((const float2*)Win)[row * 32 + w];
        uint32_t h, l;
        split2(v.x, v.y, h, l);
        sWinHi[row * KPAD + w] = h;
        sWinLo[row * KPAD + w] = l;
        v = ((const float2*)Wout)[row * 32 + w];
        split2(v.x, v.y, h, l);
        sWoutHi[row * KPAD + w] = h;
        sWoutLo[row * KPAD + w] = l;
    }
    if (tid < 64) sTheta[tid] = theta[tid];
    __syncthreads();

    const int lane = tid & 31;
    const int warp = tid >> 5;    // 0..7
    const int gr   = lane >> 2;   // group-of-4 id (row within 8)
    const int tc   = lane & 3;    // thread-in-group (col pair selector)

    const int tok0 = blockIdx.x * TILE_T + warp * 16;   // 16 tokens per warp

    // ---------------- Front-batched x loads (MLP=16), streaming ----------------
    float2 v[16];
    const float* px = x + (size_t)(tok0 + gr) * 64 + tc * 2;
#pragma unroll
    for (int kt = 0; kt < 4; kt++) {
        v[kt * 4 + 0] = ldcs2(px + kt * 16);              // (gr,   kt*16+tc*2)
        v[kt * 4 + 1] = ldcs2(px + kt * 16 + 8 * 64);     // (gr+8, kt*16+tc*2)
        v[kt * 4 + 2] = ldcs2(px + kt * 16 + 8);          // (gr,   kt*16+tc*2+8)
        v[kt * 4 + 3] = ldcs2(px + kt * 16 + 8 * 64 + 8); // (gr+8, kt*16+tc*2+8)
    }

    uint32_t ah[4][4], al[4][4];
#pragma unroll
    for (int kt = 0; kt < 4; kt++)
#pragma unroll
        for (int i = 0; i < 4; i++)
            split2(v[kt * 4 + i].x, v[kt * 4 + i].y, ah[kt][i], al[kt][i]);

    // ---------------- GEMM1: T = X @ Win^T (bf16x3, fp32 acc) ----------------
    float acc[8][4];
#pragma unroll
    for (int nt = 0; nt < 8; nt++)
#pragma unroll
        for (int i = 0; i < 4; i++) acc[nt][i] = 0.f;

#pragma unroll
    for (int kt = 0; kt < 4; kt++) {
#pragma unroll
        for (int nt = 0; nt < 8; nt++) {
            const int bidx = (nt * 8 + gr) * KPAD + kt * 8 + tc;
            const uint32_t bh0 = sWinHi[bidx], bh1 = sWinHi[bidx + 4];
            const uint32_t bl0 = sWinLo[bidx], bl1 = sWinLo[bidx + 4];
            mma16816(acc[nt], ah[kt], bh0, bh1);  // hi*hi
            mma16816(acc[nt], al[kt], bh0, bh1);  // lo*hi
            mma16816(acc[nt], ah[kt], bl0, bl1);  // hi*lo
        }
    }

    // -------- q = cos(T + theta); repack C-frags directly into A-frags --------
    uint32_t a2h[4][4], a2l[4][4];
#pragma unroll
    for (int kt2 = 0; kt2 < 4; kt2++) {
        const int ntA = 2 * kt2, ntB = 2 * kt2 + 1;
        const float tA0 = sTheta[ntA * 8 + tc * 2], tA1 = sTheta[ntA * 8 + tc * 2 + 1];
        const float tB0 = sTheta[ntB * 8 + tc * 2], tB1 = sTheta[ntB * 8 + tc * 2 + 1];
        float qa0 = __cosf(acc[ntA][0] + tA0);
        float qa1 = __cosf(acc[ntA][1] + tA1);
        float qa2 = __cosf(acc[ntA][2] + tA0);
        float qa3 = __cosf(acc[ntA][3] + tA1);
        float qb0 = __cosf(acc[ntB][0] + tB0);
        float qb1 = __cosf(acc[ntB][1] + tB1);
        float qb2 = __cosf(acc[ntB][2] + tB0);
        float qb3 = __cosf(acc[ntB][3] + tB1);
        split2(qa0, qa1, a2h[kt2][0], a2l[kt2][0]); // row gr,   k lo-half
        split2(qa2, qa3, a2h[kt2][1], a2l[kt2][1]); // row gr+8, k lo-half
        split2(qb0, qb1, a2h[kt2][2], a2l[kt2][2]); // row gr,   k hi-half
        split2(qb2, qb3, a2h[kt2][3], a2l[kt2][3]); // row gr+8, k hi-half
    }

    // ---------------- GEMM2: Y = q @ Wout^T (bf16x3, fp32 acc) ----------------
    float acc2[8][4];
#pragma unroll
    for (int nt = 0; nt < 8; nt++)
#pragma unroll
        for (int i = 0; i < 4; i++) acc2[nt][i] = 0.f;

#pragma unroll
    for (int kt2 = 0; kt2 < 4; kt2++) {
#pragma unroll
        for (int nt2 = 0; nt2 < 8; nt2++) {
            const int bidx = (nt2 * 8 + gr) * KPAD + kt2 * 8 + tc;
            const uint32_t bh0 = sWoutHi[bidx], bh1 = sWoutHi[bidx + 4];
            const uint32_t bl0 = sWoutLo[bidx], bl1 = sWoutLo[bidx + 4];
            mma16816(acc2[nt2], a2h[kt2], bh0, bh1);
            mma16816(acc2[nt2], a2l[kt2], bh0, bh1);
            mma16816(acc2[nt2], a2h[kt2], bl0, bl1);
        }
    }

    // ---------------- Store: each 4-lane group writes contiguous 32B ----------------
    const size_t r0 = (size_t)(tok0 + gr);
#pragma unroll
    for (int nt2 = 0; nt2 < 8; nt2++) {
        float* po = out + r0 * 64 + nt2 * 8 + tc * 2;
        stcs2(po,          acc2[nt2][0], acc2[nt2][1]);
        stcs2(po + 8 * 64, acc2[nt2][2], acc2[nt2][3]);
    }
}

extern "C" void kernel_launch(void* const* d_in, const int* in_sizes, int n_in,
                              void* d_out, int out_size) {
    const float* x     = (const float*)d_in[0];
    const float* W_in  = (const float*)d_in[1];
    const float* theta = (const float*)d_in[2];
    const float* W_out = (const float*)d_in[3];
    float* out = (float*)d_out;

    quantum_fused_kernel<<<NCTAS, 256>>>(x, W_in, theta, W_out, out);
}